// round 1
// baseline (speedup 1.0000x reference)
#include <cuda_runtime.h>
#include <cuda_bf16.h>
#include <cstdint>

// Problem constants
#define B_   16
#define T_   2048
#define DIN  1024
#define DPRJ 512
#define DOUT 1024
#define LORD 20
#define MROWS (B_ * T_)          // 32768

// Scratch (allocation-free: __device__ globals)
__device__ float g_x[(size_t)MROWS * DPRJ];   // x = input @ W_lin   [M, 512]
__device__ float g_m[(size_t)MROWS * DPRJ];   // m = conv(x) + x     [M, 512]

__device__ __forceinline__ float4 ld4(const float* p) {
    return *reinterpret_cast<const float4*>(p);
}

// ---------------------------------------------------------------------------
// SGEMM: C[M,N] = A[M,K] * B[K,N]  (+ bias, relu if RELU)
// BM=BN=128, BK=8, TM=TN=8, 256 threads.
// ---------------------------------------------------------------------------
template <bool RELU>
__global__ __launch_bounds__(256, 2)
void sgemm128(int M, int N, int K,
              const float* __restrict__ A,
              const float* __restrict__ Bm,
              const float* __restrict__ bias,
              float* __restrict__ C)
{
    constexpr int BM = 128, BN = 128, BK = 8, TM = 8, TN = 8;
    __shared__ float As[BK * BM];   // transposed tile
    __shared__ float Bs[BK * BN];

    const int tid  = threadIdx.x;
    const int cRow = blockIdx.y;
    const int cCol = blockIdx.x;

    const float* Ap = A + (size_t)cRow * BM * K;
    const float* Bp = Bm + (size_t)cCol * BN;

    const int innerRowA = tid >> 1;          // 0..127
    const int innerColA = (tid & 1) * 4;     // 0 or 4
    const int innerRowB = tid >> 5;          // 0..7
    const int innerColB = (tid & 31) * 4;    // 0..124

    const int threadCol = tid & 15;          // 0..15
    const int threadRow = tid >> 4;          // 0..15

    float acc[TM][TN] = {};
    float regM[TM], regN[TN];

    for (int k0 = 0; k0 < K; k0 += BK) {
        float4 a = ld4(Ap + (size_t)innerRowA * K + innerColA);
        As[(innerColA + 0) * BM + innerRowA] = a.x;
        As[(innerColA + 1) * BM + innerRowA] = a.y;
        As[(innerColA + 2) * BM + innerRowA] = a.z;
        As[(innerColA + 3) * BM + innerRowA] = a.w;
        *reinterpret_cast<float4*>(&Bs[innerRowB * BN + innerColB]) =
            ld4(Bp + (size_t)innerRowB * N + innerColB);
        __syncthreads();
        Ap += BK;
        Bp += (size_t)BK * N;

        #pragma unroll
        for (int k = 0; k < BK; k++) {
            #pragma unroll
            for (int i = 0; i < TM; i++) regM[i] = As[k * BM + threadRow * TM + i];
            #pragma unroll
            for (int j = 0; j < TN; j++) regN[j] = Bs[k * BN + threadCol * TN + j];
            #pragma unroll
            for (int i = 0; i < TM; i++)
                #pragma unroll
                for (int j = 0; j < TN; j++)
                    acc[i][j] += regM[i] * regN[j];
        }
        __syncthreads();
    }

    // Epilogue
    float breg[TN];
    if (RELU) {
        #pragma unroll
        for (int j = 0; j < TN; j++)
            breg[j] = bias[cCol * BN + threadCol * TN + j];
    }
    #pragma unroll
    for (int i = 0; i < TM; i++) {
        const int row = cRow * BM + threadRow * TM + i;
        float* crow = C + (size_t)row * N + cCol * BN + threadCol * TN;
        #pragma unroll
        for (int j = 0; j < TN; j += 4) {
            float4 v;
            v.x = acc[i][j + 0]; v.y = acc[i][j + 1];
            v.z = acc[i][j + 2]; v.w = acc[i][j + 3];
            if (RELU) {
                v.x = fmaxf(v.x + breg[j + 0], 0.f);
                v.y = fmaxf(v.y + breg[j + 1], 0.f);
                v.z = fmaxf(v.z + breg[j + 2], 0.f);
                v.w = fmaxf(v.w + breg[j + 3], 0.f);
            }
            *reinterpret_cast<float4*>(crow + j) = v;
        }
    }
}

// ---------------------------------------------------------------------------
// Depthwise causal conv (L=20) + residual.
// x layout: [B*T, P] row-major. m same. in_cache: [B, P, 19]. conv_w: [P, 20].
// Each thread owns one p, walks TCHUNK timesteps with a 19-register window.
// ---------------------------------------------------------------------------
#define TCHUNK 128

__global__ __launch_bounds__(256)
void conv_residual_kernel(const float* __restrict__ x,
                          const float* __restrict__ in_cache,
                          const float* __restrict__ conv_w,
                          float* __restrict__ m)
{
    const int p  = blockIdx.x * 256 + threadIdx.x;   // 0..511
    const int b  = blockIdx.z;
    const int t0 = blockIdx.y * TCHUNK;

    float w[LORD];
    #pragma unroll
    for (int l = 0; l < LORD; l++) w[l] = conv_w[p * LORD + l];

    // win[i] = v[t0 - 19 + i], i = 0..18; v[j] = x[b,j,p] for j>=0 else in_cache
    float win[LORD - 1];
    #pragma unroll
    for (int i = 0; i < LORD - 1; i++) {
        const int j = t0 - (LORD - 1) + i;
        if (j >= 0)
            win[i] = x[((size_t)b * T_ + j) * DPRJ + p];
        else
            win[i] = in_cache[((size_t)b * DPRJ + p) * (LORD - 1) + (j + LORD - 1)];
    }

    const float* xrow = x + ((size_t)b * T_ + t0) * DPRJ + p;
    float*       mrow = m + ((size_t)b * T_ + t0) * DPRJ + p;

    for (int t = 0; t < TCHUNK; t++) {
        const float xv = xrow[(size_t)t * DPRJ];
        float acc = fmaf(w[LORD - 1], xv, xv);     // conv tap l=19 + residual
        #pragma unroll
        for (int l = 0; l < LORD - 1; l++)
            acc = fmaf(w[l], win[l], acc);
        mrow[(size_t)t * DPRJ] = acc;
        #pragma unroll
        for (int i = 0; i < LORD - 2; i++) win[i] = win[i + 1];
        win[LORD - 2] = xv;
    }
}

// ---------------------------------------------------------------------------
// out_cache[b,p,i] = x[b, T-19+i, p]
// ---------------------------------------------------------------------------
__global__ void cache_kernel(const float* __restrict__ x,
                             float* __restrict__ out_cache)
{
    const int idx = blockIdx.x * blockDim.x + threadIdx.x;
    const int total = B_ * DPRJ * (LORD - 1);
    if (idx >= total) return;
    const int i = idx % (LORD - 1);
    const int p = (idx / (LORD - 1)) % DPRJ;
    const int b = idx / ((LORD - 1) * DPRJ);
    out_cache[idx] = x[((size_t)b * T_ + (T_ - (LORD - 1) + i)) * DPRJ + p];
}

// ---------------------------------------------------------------------------
extern "C" void kernel_launch(void* const* d_in, const int* in_sizes, int n_in,
                              void* d_out, int out_size)
{
    const float* input    = (const float*)d_in[0];  // [16, 2048, 1024]
    const float* in_cache = (const float*)d_in[1];  // [16, 512, 19]
    const float* W_lin    = (const float*)d_in[2];  // [1024, 512]
    const float* conv_w   = (const float*)d_in[3];  // [512, 20]
    const float* W_aff    = (const float*)d_in[4];  // [512, 1024]
    const float* b_aff    = (const float*)d_in[5];  // [1024]

    float* out       = (float*)d_out;                        // [16,2048,1024]
    float* out_cache = out + (size_t)B_ * T_ * DOUT;         // [16,512,19]

    float* xbuf; float* mbuf;
    cudaGetSymbolAddress((void**)&xbuf, g_x);
    cudaGetSymbolAddress((void**)&mbuf, g_m);

    // 1) x = input @ W_lin      M=32768, N=512, K=1024
    {
        dim3 grid(DPRJ / 128, MROWS / 128);
        sgemm128<false><<<grid, 256>>>(MROWS, DPRJ, DIN, input, W_lin, nullptr, xbuf);
    }

    // 2) m = depthwise_conv(x) + x   (and out_cache)
    {
        dim3 grid(DPRJ / 256, T_ / TCHUNK, B_);
        conv_residual_kernel<<<grid, 256>>>(xbuf, in_cache, conv_w, mbuf);
        const int total = B_ * DPRJ * (LORD - 1);
        cache_kernel<<<(total + 255) / 256, 256>>>(xbuf, out_cache);
    }

    // 3) out = relu(m @ W_aff + b_aff)   M=32768, N=1024, K=512
    {
        dim3 grid(DOUT / 128, MROWS / 128);
        sgemm128<true><<<grid, 256>>>(MROWS, DOUT, DPRJ, mbuf, W_aff, b_aff, out);
    }
}

// round 2
// speedup vs baseline: 1.0013x; 1.0013x over previous
#include <cuda_runtime.h>
#include <cuda_bf16.h>
#include <cstdint>

// Problem constants
#define B_   16
#define T_   2048
#define DIN  1024
#define DPRJ 512
#define DOUT 1024
#define LORD 20
#define MROWS (B_ * T_)          // 32768

// Scratch (allocation-free: __device__ globals)
__device__ float g_x[(size_t)MROWS * DPRJ];   // x = input @ W_lin   [M, 512]
__device__ float g_m[(size_t)MROWS * DPRJ];   // m = conv(x) + x     [M, 512]

__device__ __forceinline__ float4 ld4(const float* p) {
    return *reinterpret_cast<const float4*>(p);
}

// ---------------------------------------------------------------------------
// SGEMM: C[M,N] = A[M,K] * B[K,N]  (+ bias, relu if RELU)
// BM=BN=128, BK=8, TM=TN=8, 256 threads.
// ---------------------------------------------------------------------------
template <bool RELU>
__global__ __launch_bounds__(256, 2)
void sgemm128(int M, int N, int K,
              const float* __restrict__ A,
              const float* __restrict__ Bm,
              const float* __restrict__ bias,
              float* __restrict__ C)
{
    constexpr int BM = 128, BN = 128, BK = 8, TM = 8, TN = 8;
    __shared__ float As[BK * BM];   // transposed tile
    __shared__ float Bs[BK * BN];

    const int tid  = threadIdx.x;
    const int cRow = blockIdx.y;
    const int cCol = blockIdx.x;

    const float* Ap = A + (size_t)cRow * BM * K;
    const float* Bp = Bm + (size_t)cCol * BN;

    const int innerRowA = tid >> 1;          // 0..127
    const int innerColA = (tid & 1) * 4;     // 0 or 4
    const int innerRowB = tid >> 5;          // 0..7
    const int innerColB = (tid & 31) * 4;    // 0..124

    const int threadCol = tid & 15;          // 0..15
    const int threadRow = tid >> 4;          // 0..15

    float acc[TM][TN] = {};
    float regM[TM], regN[TN];

    for (int k0 = 0; k0 < K; k0 += BK) {
        float4 a = ld4(Ap + (size_t)innerRowA * K + innerColA);
        As[(innerColA + 0) * BM + innerRowA] = a.x;
        As[(innerColA + 1) * BM + innerRowA] = a.y;
        As[(innerColA + 2) * BM + innerRowA] = a.z;
        As[(innerColA + 3) * BM + innerRowA] = a.w;
        *reinterpret_cast<float4*>(&Bs[innerRowB * BN + innerColB]) =
            ld4(Bp + (size_t)innerRowB * N + innerColB);
        __syncthreads();
        Ap += BK;
        Bp += (size_t)BK * N;

        #pragma unroll
        for (int k = 0; k < BK; k++) {
            #pragma unroll
            for (int i = 0; i < TM; i++) regM[i] = As[k * BM + threadRow * TM + i];
            #pragma unroll
            for (int j = 0; j < TN; j++) regN[j] = Bs[k * BN + threadCol * TN + j];
            #pragma unroll
            for (int i = 0; i < TM; i++)
                #pragma unroll
                for (int j = 0; j < TN; j++)
                    acc[i][j] += regM[i] * regN[j];
        }
        __syncthreads();
    }

    // Epilogue
    float breg[TN];
    if (RELU) {
        #pragma unroll
        for (int j = 0; j < TN; j++)
            breg[j] = bias[cCol * BN + threadCol * TN + j];
    }
    #pragma unroll
    for (int i = 0; i < TM; i++) {
        const int row = cRow * BM + threadRow * TM + i;
        float* crow = C + (size_t)row * N + cCol * BN + threadCol * TN;
        #pragma unroll
        for (int j = 0; j < TN; j += 4) {
            float4 v;
            v.x = acc[i][j + 0]; v.y = acc[i][j + 1];
            v.z = acc[i][j + 2]; v.w = acc[i][j + 3];
            if (RELU) {
                v.x = fmaxf(v.x + breg[j + 0], 0.f);
                v.y = fmaxf(v.y + breg[j + 1], 0.f);
                v.z = fmaxf(v.z + breg[j + 2], 0.f);
                v.w = fmaxf(v.w + breg[j + 3], 0.f);
            }
            *reinterpret_cast<float4*>(crow + j) = v;
        }
    }
}

// ---------------------------------------------------------------------------
// Depthwise causal conv (L=20) + residual.
// x layout: [B*T, P] row-major. m same. in_cache: [B, P, 19]. conv_w: [P, 20].
// Each thread owns one p, walks TCHUNK timesteps with a 19-register window.
// ---------------------------------------------------------------------------
#define TCHUNK 128

__global__ __launch_bounds__(256)
void conv_residual_kernel(const float* __restrict__ x,
                          const float* __restrict__ in_cache,
                          const float* __restrict__ conv_w,
                          float* __restrict__ m)
{
    const int p  = blockIdx.x * 256 + threadIdx.x;   // 0..511
    const int b  = blockIdx.z;
    const int t0 = blockIdx.y * TCHUNK;

    float w[LORD];
    #pragma unroll
    for (int l = 0; l < LORD; l++) w[l] = conv_w[p * LORD + l];

    // win[i] = v[t0 - 19 + i], i = 0..18; v[j] = x[b,j,p] for j>=0 else in_cache
    float win[LORD - 1];
    #pragma unroll
    for (int i = 0; i < LORD - 1; i++) {
        const int j = t0 - (LORD - 1) + i;
        if (j >= 0)
            win[i] = x[((size_t)b * T_ + j) * DPRJ + p];
        else
            win[i] = in_cache[((size_t)b * DPRJ + p) * (LORD - 1) + (j + LORD - 1)];
    }

    const float* xrow = x + ((size_t)b * T_ + t0) * DPRJ + p;
    float*       mrow = m + ((size_t)b * T_ + t0) * DPRJ + p;

    for (int t = 0; t < TCHUNK; t++) {
        const float xv = xrow[(size_t)t * DPRJ];
        float acc = fmaf(w[LORD - 1], xv, xv);     // conv tap l=19 + residual
        #pragma unroll
        for (int l = 0; l < LORD - 1; l++)
            acc = fmaf(w[l], win[l], acc);
        mrow[(size_t)t * DPRJ] = acc;
        #pragma unroll
        for (int i = 0; i < LORD - 2; i++) win[i] = win[i + 1];
        win[LORD - 2] = xv;
    }
}

// ---------------------------------------------------------------------------
// out_cache[b,p,i] = x[b, T-19+i, p]
// ---------------------------------------------------------------------------
__global__ void cache_kernel(const float* __restrict__ x,
                             float* __restrict__ out_cache)
{
    const int idx = blockIdx.x * blockDim.x + threadIdx.x;
    const int total = B_ * DPRJ * (LORD - 1);
    if (idx >= total) return;
    const int i = idx % (LORD - 1);
    const int p = (idx / (LORD - 1)) % DPRJ;
    const int b = idx / ((LORD - 1) * DPRJ);
    out_cache[idx] = x[((size_t)b * T_ + (T_ - (LORD - 1) + i)) * DPRJ + p];
}

// ---------------------------------------------------------------------------
extern "C" void kernel_launch(void* const* d_in, const int* in_sizes, int n_in,
                              void* d_out, int out_size)
{
    const float* input    = (const float*)d_in[0];  // [16, 2048, 1024]
    const float* in_cache = (const float*)d_in[1];  // [16, 512, 19]
    const float* W_lin    = (const float*)d_in[2];  // [1024, 512]
    const float* conv_w   = (const float*)d_in[3];  // [512, 20]
    const float* W_aff    = (const float*)d_in[4];  // [512, 1024]
    const float* b_aff    = (const float*)d_in[5];  // [1024]

    float* out       = (float*)d_out;                        // [16,2048,1024]
    float* out_cache = out + (size_t)B_ * T_ * DOUT;         // [16,512,19]

    float* xbuf; float* mbuf;
    cudaGetSymbolAddress((void**)&xbuf, g_x);
    cudaGetSymbolAddress((void**)&mbuf, g_m);

    // 1) x = input @ W_lin      M=32768, N=512, K=1024
    {
        dim3 grid(DPRJ / 128, MROWS / 128);
        sgemm128<false><<<grid, 256>>>(MROWS, DPRJ, DIN, input, W_lin, nullptr, xbuf);
    }

    // 2) m = depthwise_conv(x) + x   (and out_cache)
    {
        dim3 grid(DPRJ / 256, T_ / TCHUNK, B_);
        conv_residual_kernel<<<grid, 256>>>(xbuf, in_cache, conv_w, mbuf);
        const int total = B_ * DPRJ * (LORD - 1);
        cache_kernel<<<(total + 255) / 256, 256>>>(xbuf, out_cache);
    }

    // 3) out = relu(m @ W_aff + b_aff)   M=32768, N=1024, K=512
    {
        dim3 grid(DOUT / 128, MROWS / 128);
        sgemm128<true><<<grid, 256>>>(MROWS, DOUT, DPRJ, mbuf, W_aff, b_aff, out);
    }
}

// round 3
// speedup vs baseline: 1.0016x; 1.0002x over previous
#include <cuda_runtime.h>
#include <cuda_bf16.h>
#include <cstdint>

// Problem constants
#define B_   16
#define T_   2048
#define DIN  1024
#define DPRJ 512
#define DOUT 1024
#define LORD 20
#define MROWS (B_ * T_)          // 32768

// Scratch (allocation-free: __device__ globals)
__device__ float g_x[(size_t)MROWS * DPRJ];   // x = input @ W_lin   [M, 512]
__device__ float g_m[(size_t)MROWS * DPRJ];   // m = conv(x) + x     [M, 512]

__device__ __forceinline__ float4 ld4(const float* p) {
    return *reinterpret_cast<const float4*>(p);
}

// ---------------------------------------------------------------------------
// SGEMM: C[M,N] = A[M,K] * B[K,N]  (+ bias, relu if RELU)
// BM=BN=128, BK=8, TM=TN=8, 256 threads.
// ---------------------------------------------------------------------------
template <bool RELU>
__global__ __launch_bounds__(256, 2)
void sgemm128(int M, int N, int K,
              const float* __restrict__ A,
              const float* __restrict__ Bm,
              const float* __restrict__ bias,
              float* __restrict__ C)
{
    constexpr int BM = 128, BN = 128, BK = 8, TM = 8, TN = 8;
    __shared__ float As[BK * BM];   // transposed tile
    __shared__ float Bs[BK * BN];

    const int tid  = threadIdx.x;
    const int cRow = blockIdx.y;
    const int cCol = blockIdx.x;

    const float* Ap = A + (size_t)cRow * BM * K;
    const float* Bp = Bm + (size_t)cCol * BN;

    const int innerRowA = tid >> 1;          // 0..127
    const int innerColA = (tid & 1) * 4;     // 0 or 4
    const int innerRowB = tid >> 5;          // 0..7
    const int innerColB = (tid & 31) * 4;    // 0..124

    const int threadCol = tid & 15;          // 0..15
    const int threadRow = tid >> 4;          // 0..15

    float acc[TM][TN] = {};
    float regM[TM], regN[TN];

    for (int k0 = 0; k0 < K; k0 += BK) {
        float4 a = ld4(Ap + (size_t)innerRowA * K + innerColA);
        As[(innerColA + 0) * BM + innerRowA] = a.x;
        As[(innerColA + 1) * BM + innerRowA] = a.y;
        As[(innerColA + 2) * BM + innerRowA] = a.z;
        As[(innerColA + 3) * BM + innerRowA] = a.w;
        *reinterpret_cast<float4*>(&Bs[innerRowB * BN + innerColB]) =
            ld4(Bp + (size_t)innerRowB * N + innerColB);
        __syncthreads();
        Ap += BK;
        Bp += (size_t)BK * N;

        #pragma unroll
        for (int k = 0; k < BK; k++) {
            #pragma unroll
            for (int i = 0; i < TM; i++) regM[i] = As[k * BM + threadRow * TM + i];
            #pragma unroll
            for (int j = 0; j < TN; j++) regN[j] = Bs[k * BN + threadCol * TN + j];
            #pragma unroll
            for (int i = 0; i < TM; i++)
                #pragma unroll
                for (int j = 0; j < TN; j++)
                    acc[i][j] += regM[i] * regN[j];
        }
        __syncthreads();
    }

    // Epilogue
    float breg[TN];
    if (RELU) {
        #pragma unroll
        for (int j = 0; j < TN; j++)
            breg[j] = bias[cCol * BN + threadCol * TN + j];
    }
    #pragma unroll
    for (int i = 0; i < TM; i++) {
        const int row = cRow * BM + threadRow * TM + i;
        float* crow = C + (size_t)row * N + cCol * BN + threadCol * TN;
        #pragma unroll
        for (int j = 0; j < TN; j += 4) {
            float4 v;
            v.x = acc[i][j + 0]; v.y = acc[i][j + 1];
            v.z = acc[i][j + 2]; v.w = acc[i][j + 3];
            if (RELU) {
                v.x = fmaxf(v.x + breg[j + 0], 0.f);
                v.y = fmaxf(v.y + breg[j + 1], 0.f);
                v.z = fmaxf(v.z + breg[j + 2], 0.f);
                v.w = fmaxf(v.w + breg[j + 3], 0.f);
            }
            *reinterpret_cast<float4*>(crow + j) = v;
        }
    }
}

// ---------------------------------------------------------------------------
// Depthwise causal conv (L=20) + residual.
// x layout: [B*T, P] row-major. m same. in_cache: [B, P, 19]. conv_w: [P, 20].
// Each thread owns one p, walks TCHUNK timesteps with a 19-register window.
// ---------------------------------------------------------------------------
#define TCHUNK 128

__global__ __launch_bounds__(256)
void conv_residual_kernel(const float* __restrict__ x,
                          const float* __restrict__ in_cache,
                          const float* __restrict__ conv_w,
                          float* __restrict__ m)
{
    const int p  = blockIdx.x * 256 + threadIdx.x;   // 0..511
    const int b  = blockIdx.z;
    const int t0 = blockIdx.y * TCHUNK;

    float w[LORD];
    #pragma unroll
    for (int l = 0; l < LORD; l++) w[l] = conv_w[p * LORD + l];

    // win[i] = v[t0 - 19 + i], i = 0..18; v[j] = x[b,j,p] for j>=0 else in_cache
    float win[LORD - 1];
    #pragma unroll
    for (int i = 0; i < LORD - 1; i++) {
        const int j = t0 - (LORD - 1) + i;
        if (j >= 0)
            win[i] = x[((size_t)b * T_ + j) * DPRJ + p];
        else
            win[i] = in_cache[((size_t)b * DPRJ + p) * (LORD - 1) + (j + LORD - 1)];
    }

    const float* xrow = x + ((size_t)b * T_ + t0) * DPRJ + p;
    float*       mrow = m + ((size_t)b * T_ + t0) * DPRJ + p;

    for (int t = 0; t < TCHUNK; t++) {
        const float xv = xrow[(size_t)t * DPRJ];
        float acc = fmaf(w[LORD - 1], xv, xv);     // conv tap l=19 + residual
        #pragma unroll
        for (int l = 0; l < LORD - 1; l++)
            acc = fmaf(w[l], win[l], acc);
        mrow[(size_t)t * DPRJ] = acc;
        #pragma unroll
        for (int i = 0; i < LORD - 2; i++) win[i] = win[i + 1];
        win[LORD - 2] = xv;
    }
}

// ---------------------------------------------------------------------------
// out_cache[b,p,i] = x[b, T-19+i, p]
// ---------------------------------------------------------------------------
__global__ void cache_kernel(const float* __restrict__ x,
                             float* __restrict__ out_cache)
{
    const int idx = blockIdx.x * blockDim.x + threadIdx.x;
    const int total = B_ * DPRJ * (LORD - 1);
    if (idx >= total) return;
    const int i = idx % (LORD - 1);
    const int p = (idx / (LORD - 1)) % DPRJ;
    const int b = idx / ((LORD - 1) * DPRJ);
    out_cache[idx] = x[((size_t)b * T_ + (T_ - (LORD - 1) + i)) * DPRJ + p];
}

// ---------------------------------------------------------------------------
extern "C" void kernel_launch(void* const* d_in, const int* in_sizes, int n_in,
                              void* d_out, int out_size)
{
    const float* input    = (const float*)d_in[0];  // [16, 2048, 1024]
    const float* in_cache = (const float*)d_in[1];  // [16, 512, 19]
    const float* W_lin    = (const float*)d_in[2];  // [1024, 512]
    const float* conv_w   = (const float*)d_in[3];  // [512, 20]
    const float* W_aff    = (const float*)d_in[4];  // [512, 1024]
    const float* b_aff    = (const float*)d_in[5];  // [1024]

    float* out       = (float*)d_out;                        // [16,2048,1024]
    float* out_cache = out + (size_t)B_ * T_ * DOUT;         // [16,512,19]

    float* xbuf; float* mbuf;
    cudaGetSymbolAddress((void**)&xbuf, g_x);
    cudaGetSymbolAddress((void**)&mbuf, g_m);

    // 1) x = input @ W_lin      M=32768, N=512, K=1024
    {
        dim3 grid(DPRJ / 128, MROWS / 128);
        sgemm128<false><<<grid, 256>>>(MROWS, DPRJ, DIN, input, W_lin, nullptr, xbuf);
    }

    // 2) m = depthwise_conv(x) + x   (and out_cache)
    {
        dim3 grid(DPRJ / 256, T_ / TCHUNK, B_);
        conv_residual_kernel<<<grid, 256>>>(xbuf, in_cache, conv_w, mbuf);
        const int total = B_ * DPRJ * (LORD - 1);
        cache_kernel<<<(total + 255) / 256, 256>>>(xbuf, out_cache);
    }

    // 3) out = relu(m @ W_aff + b_aff)   M=32768, N=1024, K=512
    {
        dim3 grid(DOUT / 128, MROWS / 128);
        sgemm128<true><<<grid, 256>>>(MROWS, DOUT, DPRJ, mbuf, W_aff, b_aff, out);
    }
}